// round 12
// baseline (speedup 1.0000x reference)
#include <cuda_runtime.h>
#include <cuda_fp16.h>
#include <stdint.h>

#define BATCH   32
#define HDIM    4096
#define IDIM    2048
#define NCOLS   4096
#define GSZ     128

#define KSPLIT  8
#define MTILE   64       // weight columns per block
#define KCHUNK  64       // K per pipeline stage
#define THREADS 256
#define STAGES  4        // smem ring stages (3 chunks in flight)

// ---------------- scratch ------------------------------------------------
__device__ __align__(16) __half g_xh[BATCH * HDIM];     // x fp16 [b][k]
__device__ __align__(16) __half g_acth[BATCH * IDIM];   // act fp16 [b][i]
__device__ float g_hpart[KSPLIT][NCOLS * BATCH];        // gemm1 partials [s][n][b]
__device__ float g_opart[KSPLIT][NCOLS * BATCH];        // gemm2 partials [s][n][b]

// ---------------- helpers -------------------------------------------------
__device__ __forceinline__ uint32_t smem_u32(const void* p) {
    uint32_t a;
    asm("{ .reg .u64 t; cvta.to.shared.u64 t, %1; cvt.u32.u64 %0, t; }"
        : "=r"(a) : "l"(p));
    return a;
}
#define CP16(dst, src) \
    asm volatile("cp.async.cg.shared.global [%0], [%1], 16;" \
                 :: "r"(dst), "l"(src) : "memory")
#define CP_COMMIT() asm volatile("cp.async.commit_group;" ::: "memory")
#define CP_WAIT2()  asm volatile("cp.async.wait_group 2;"  ::: "memory")

__device__ __forceinline__ void ldsm_x4(uint32_t& r0, uint32_t& r1,
                                        uint32_t& r2, uint32_t& r3, uint32_t addr) {
    asm volatile("ldmatrix.sync.aligned.m8n8.x4.shared.b16 {%0,%1,%2,%3}, [%4];"
                 : "=r"(r0), "=r"(r1), "=r"(r2), "=r"(r3) : "r"(addr));
}
__device__ __forceinline__ void mma_16816(float* c, const uint32_t* a, const uint32_t* b) {
    asm volatile(
        "mma.sync.aligned.m16n8k16.row.col.f32.f16.f16.f32 "
        "{%0,%1,%2,%3}, {%4,%5,%6,%7}, {%8,%9}, {%0,%1,%2,%3};"
        : "+f"(c[0]), "+f"(c[1]), "+f"(c[2]), "+f"(c[3])
        : "r"(a[0]), "r"(a[1]), "r"(a[2]), "r"(a[3]), "r"(b[0]), "r"(b[1]));
}

// Dequant byte sel of packed word w -> fp16x2 (k pair), scaled by sf2.
// fp16 pattern (s<<15)|(eem<<9) == fp4_value * 2^-14 exactly; sf2 = half2(scale*2^14).
__device__ __forceinline__ uint32_t dqb(uint32_t w, uint32_t sel, uint32_t sf2) {
    uint32_t t, r;
    asm("prmt.b32 %0, %1, %1, %2;" : "=r"(t) : "r"(w), "r"(sel));
    uint32_t h = ((t << 9) & 0x00000E00u) | ((t << 4) & 0x00008000u)
               | ((t << 5) & 0x0E000000u) | (t & 0x80000000u);
    asm("mul.f16x2 %0, %1, %2;" : "=r"(r) : "r"(h), "r"(sf2));
    return r;
}

// ---------------- prep: x f32 -> fp16 ------------------------------------
__global__ void __launch_bounds__(512) prep_x_kernel(const float* __restrict__ x) {
    int idx = blockIdx.x * 512 + threadIdx.x;
    g_xh[idx] = __float2half_rn(x[idx]);   // exact: x was fp16 originally
}

// ---------------- cp.async HMMA dequant-GEMM (k-split warp pairs) --------
// partial[n][b] += sum_k dequant(W[k][n]) * act[b][k]
// 8 warps: wid&3 = m16 slice, wid>>2 = k16-step half. Warp pairs (w, w+4)
// accumulate disjoint k and merge through smem at the end.
template <int KDIM, bool PHASE1>
__global__ void __launch_bounds__(THREADS) gemm_mma_kernel(
    const int*   __restrict__ packed,   // [KDIM/8][NCOLS]
    const float* __restrict__ scales)   // [KDIM/GSZ][NCOLS]
{
    constexpr int NCH = (KDIM / KSPLIT) / KCHUNK;   // 8 (gemm1) / 4 (gemm2)

    __shared__ __align__(16) uint32_t Ap [STAGES][8 * MTILE];       // packed W, 8 KB
    __shared__ __align__(16) __half   Bsh[STAGES][BATCH * KCHUNK];  // 16 KB
    __shared__ __align__(16) float    Scs[STAGES][MTILE];           // 1 KB

    const int tid  = threadIdx.x;
    const int wid  = tid >> 5;
    const int lane = tid & 31;

    const int n_base  = blockIdx.x * MTILE;
    const int k_begin = blockIdx.y * (KDIM / KSPLIT);

    // ---- cp.async source/dst mapping (256 threads) ----
    // A: tid<128 -> (k8 row r = tid>>4, 4 cols n4 = (tid&15)*4), one 16B copy
    const int r  = (tid & 127) >> 4;
    const int n4 = (tid & 15) * 4;
    const uint32_t* asrc0 = (const uint32_t*)packed
                          + (size_t)((k_begin >> 3) + r) * NCOLS + n_base + n4;
    // B: all threads -> (row brow = tid>>3, 16B chunk bcx = tid&7), swizzled dst
    const int brow = tid >> 3;
    const int bcx  = tid & 7;
    const __half* __restrict__ Bsrc = PHASE1 ? g_xh : g_acth;
    const __half* bsrc0 = Bsrc + (size_t)brow * KDIM + k_begin + bcx * 8;
    uint32_t adst[STAGES], bdst[STAGES], sdst[STAGES];
    #pragma unroll
    for (int s = 0; s < STAGES; ++s) {
        adst[s] = smem_u32(&Ap[s][r * MTILE + n4]);
        bdst[s] = smem_u32(&Bsh[s][brow * KCHUNK + ((bcx ^ (brow & 7)) * 8)]);
        sdst[s] = smem_u32(&Scs[s][(tid & 15) * 4]);
    }
    const float* ssrc_base = scales + (size_t)(k_begin >> 7) * NCOLS + n_base + (tid & 15) * 4;

    auto issue = [&](int c, int st) {
        if (tid < 128) CP16(adst[st], asrc0 + (size_t)c * 8 * NCOLS);
        CP16(bdst[st], bsrc0 + (size_t)c * KCHUNK);
        if (tid < 16)  CP16(sdst[st], ssrc_base + (size_t)(c >> 1) * NCOLS);
    };

    // ---- prologue: 3 chunks in flight ----
    issue(0, 0); CP_COMMIT();
    issue(1, 1); CP_COMMIT();
    issue(2, 2); CP_COMMIT();

    // ---- MMA lane addressing ----
    float acc[4][4] = {};
    const int sub = lane >> 3, l7 = lane & 7;
    const int mslice = wid & 3;
    const int kh     = wid >> 2;               // k16-step half
    const int mrow = mslice * 16;
    const int n0l  = mrow + (lane >> 2);       // A fragment rows (tile-local n)
    const int n1l  = n0l + 8;
    const uint32_t sel = (uint32_t)(lane & 3) * 0x1111u;
    const int bn0 = l7 + (sub >> 1) * 8;       // B ldmatrix row base
    const int bcx_off = sub & 1;

    #pragma unroll
    for (int c = 0; c < NCH; ++c) {
        CP_WAIT2();           // chunk c's group (and all before) complete
        __syncthreads();      // visible to all; prior compute on reused stage done
        if (c + 3 < NCH) issue(c + 3, (c + 3) & (STAGES - 1));
        CP_COMMIT();          // commit every iter (uniform group count)

        const int st = c & (STAGES - 1);
        const uint32_t* ap = &Ap[st][0];
        const uint32_t Bb = smem_u32(&Bsh[st][0]);

        // per-row scales for this k-group (2^14 folded, exact pow2)
        const uint32_t sf0 = (uint32_t)__half_as_ushort(
            __float2half_rn(Scs[st][n0l] * 16384.0f)) * 0x00010001u;
        const uint32_t sf1 = (uint32_t)__half_as_ushort(
            __float2half_rn(Scs[st][n1l] * 16384.0f)) * 0x00010001u;

        #pragma unroll
        for (int s = 0; s < 2; ++s) {
            const int ks = kh * 2 + s;          // this warp's k16 steps
            // A fragment: dequant directly from packed smem words
            uint32_t a[4];
            {
                const uint32_t w00 = ap[(2 * ks)     * MTILE + n0l];
                const uint32_t w10 = ap[(2 * ks)     * MTILE + n1l];
                const uint32_t w01 = ap[(2 * ks + 1) * MTILE + n0l];
                const uint32_t w11 = ap[(2 * ks + 1) * MTILE + n1l];
                a[0] = dqb(w00, sel, sf0);
                a[1] = dqb(w10, sel, sf1);
                a[2] = dqb(w01, sel, sf0);
                a[3] = dqb(w11, sel, sf1);
            }
            // B fragments
            uint32_t b0[4], b1[4];
            const int bcxs = ks * 2 + bcx_off;
            {
                const int n = bn0;
                ldsm_x4(b0[0], b0[1], b0[2], b0[3],
                        Bb + (uint32_t)(n * (KCHUNK * 2))
                           + (uint32_t)((bcxs ^ (n & 7)) << 4));
            }
            {
                const int n = bn0 + 16;
                ldsm_x4(b1[0], b1[1], b1[2], b1[3],
                        Bb + (uint32_t)(n * (KCHUNK * 2))
                           + (uint32_t)((bcxs ^ (n & 7)) << 4));
            }
            mma_16816(acc[0], a, &b0[0]);
            mma_16816(acc[1], a, &b0[2]);
            mma_16816(acc[2], a, &b1[0]);
            mma_16816(acc[3], a, &b1[2]);
        }
    }

    // ---- merge k-half accumulators through smem (A stage is dead now) ----
    __syncthreads();
    float* red = (float*)&Ap[0][0];   // 4 slices x 32 lanes x 16 floats = 8 KB
    if (kh == 1) {
        float* dst = red + (mslice * 32 + lane) * 16;
        #pragma unroll
        for (int t = 0; t < 4; ++t)
            #pragma unroll
            for (int i = 0; i < 4; ++i)
                dst[t * 4 + i] = acc[t][i];
    }
    __syncthreads();
    if (kh == 1) return;
    {
        const float* src = red + (mslice * 32 + lane) * 16;
        #pragma unroll
        for (int t = 0; t < 4; ++t)
            #pragma unroll
            for (int i = 0; i < 4; ++i)
                acc[t][i] += src[t * 4 + i];
    }

    // ---- epilogue: D fragments -> partials [n][b] ----
    float* partp = (PHASE1 ? &g_hpart[0][0] : &g_opart[0][0])
                  + (size_t)blockIdx.y * (NCOLS * BATCH);
    const int gq = lane >> 2, tq = lane & 3;
    const int nrow0 = n_base + mrow + gq;
    #pragma unroll
    for (int t = 0; t < 4; ++t) {
        const int bcol = t * 8 + tq * 2;
        *(float2*)&partp[(size_t)nrow0 * BATCH + bcol]       = make_float2(acc[t][0], acc[t][1]);
        *(float2*)&partp[(size_t)(nrow0 + 8) * BATCH + bcol] = make_float2(acc[t][2], acc[t][3]);
    }
}

// ---------------- SwiGLU: reduce gemm1 partials -> act fp16 [b][i] -------
__global__ void __launch_bounds__(256) swiglu_kernel() {
    __shared__ float s_act[8][33];
    const int i0 = blockIdx.x * 8;
    const int b  = threadIdx.x & 31;
    const int il = threadIdx.x >> 5;          // 0..7
    {
        const size_t ng = (size_t)(i0 + il) * BATCH + b;
        float hg = 0.f, hu = 0.f;
        #pragma unroll
        for (int s = 0; s < KSPLIT; ++s) {
            hg += g_hpart[s][ng];
            hu += g_hpart[s][ng + (size_t)IDIM * BATCH];
        }
        const float sig = 1.0f / (1.0f + __expf(-hg));
        s_act[il][b] = hg * sig * hu;
    }
    __syncthreads();
    const int bb = threadIdx.x >> 3;          // 0..31
    const int pp = threadIdx.x & 3;           // 0..3 half2 pairs
    if ((threadIdx.x & 4) == 0) {
        __half2 h = __float22half2_rn(make_float2(s_act[pp * 2][bb], s_act[pp * 2 + 1][bb]));
        *(__half2*)&g_acth[(size_t)bb * IDIM + i0 + pp * 2] = h;
    }
}

// ---------------- reduce gemm2 partials [n][b] -> out [b][n] f32 ---------
__global__ void __launch_bounds__(256) reduce_out_kernel(float* __restrict__ out) {
    __shared__ float s_o[16][33];
    const int h0 = blockIdx.x * 16;
    const int b  = threadIdx.x & 31;
    const int hl = threadIdx.x >> 5;          // 0..7
    {
        const size_t ng0 = (size_t)(h0 + hl) * BATCH + b;
        const size_t ng1 = (size_t)(h0 + hl + 8) * BATCH + b;
        float s0 = 0.f, s1 = 0.f;
        #pragma unroll
        for (int sp = 0; sp < KSPLIT; ++sp) {
            s0 += g_opart[sp][ng0];
            s1 += g_opart[sp][ng1];
        }
        s_o[hl][b]     = s0;
        s_o[hl + 8][b] = s1;
    }
    __syncthreads();
    const int bb = threadIdx.x >> 3;          // 0..31
    const int h2 = threadIdx.x & 7;           // 0..7
    out[(size_t)bb * NCOLS + h0 + h2] =
        __half2float(__float2half_rn(s_o[h2][bb]));
    out[(size_t)bb * NCOLS + h0 + h2 + 8] =
        __half2float(__float2half_rn(s_o[h2 + 8][bb]));
}

// ---------------- launch --------------------------------------------------
extern "C" void kernel_launch(void* const* d_in, const int* in_sizes, int n_in,
                              void* d_out, int out_size) {
    const float* x   = (const float*)d_in[0];
    const int*   gup = (const int*)  d_in[1];
    const float* gus = (const float*)d_in[2];
    const int*   dwn = (const int*)  d_in[3];
    const float* dws = (const float*)d_in[4];
    float* out = (float*)d_out;

    prep_x_kernel<<<(BATCH * HDIM) / 512, 512>>>(x);

    gemm_mma_kernel<HDIM, true><<<dim3(NCOLS / MTILE, KSPLIT), THREADS>>>(gup, gus);

    swiglu_kernel<<<IDIM / 8, 256>>>();

    gemm_mma_kernel<IDIM, false><<<dim3(NCOLS / MTILE, KSPLIT), THREADS>>>(dwn, dws);

    reduce_out_kernel<<<NCOLS / 16, 256>>>(out);
}

// round 13
// speedup vs baseline: 1.1001x; 1.1001x over previous
#include <cuda_runtime.h>
#include <cuda_fp16.h>
#include <stdint.h>

#define BATCH   32
#define HDIM    4096
#define IDIM    2048
#define NCOLS   4096
#define GSZ     128

#define KSPLIT  16
#define MTILE   64       // weight columns per block
#define KCHUNK  64       // K per pipeline stage
#define THREADS 128
#define STAGES  4        // smem ring stages (up to 3 chunks in flight)

// ---------------- scratch ------------------------------------------------
__device__ __align__(16) __half g_xh[BATCH * HDIM];     // x fp16 [b][k]
__device__ __align__(16) __half g_acth[BATCH * IDIM];   // act fp16 [b][i]
__device__ float g_hpart[KSPLIT][NCOLS * BATCH];        // gemm1 partials [s][n][b]
__device__ float g_opart[KSPLIT][NCOLS * BATCH];        // gemm2 partials [s][n][b]

// ---------------- helpers -------------------------------------------------
__device__ __forceinline__ uint32_t smem_u32(const void* p) {
    uint32_t a;
    asm("{ .reg .u64 t; cvta.to.shared.u64 t, %1; cvt.u32.u64 %0, t; }"
        : "=r"(a) : "l"(p));
    return a;
}
#define CP16(dst, src) \
    asm volatile("cp.async.cg.shared.global [%0], [%1], 16;" \
                 :: "r"(dst), "l"(src) : "memory")
#define CP_COMMIT() asm volatile("cp.async.commit_group;" ::: "memory")
#define CP_WAIT2()  asm volatile("cp.async.wait_group 2;"  ::: "memory")

__device__ __forceinline__ void ldsm_x4(uint32_t& r0, uint32_t& r1,
                                        uint32_t& r2, uint32_t& r3, uint32_t addr) {
    asm volatile("ldmatrix.sync.aligned.m8n8.x4.shared.b16 {%0,%1,%2,%3}, [%4];"
                 : "=r"(r0), "=r"(r1), "=r"(r2), "=r"(r3) : "r"(addr));
}
__device__ __forceinline__ void mma_16816(float* c, const uint32_t* a, const uint32_t* b) {
    asm volatile(
        "mma.sync.aligned.m16n8k16.row.col.f32.f16.f16.f32 "
        "{%0,%1,%2,%3}, {%4,%5,%6,%7}, {%8,%9}, {%0,%1,%2,%3};"
        : "+f"(c[0]), "+f"(c[1]), "+f"(c[2]), "+f"(c[3])
        : "r"(a[0]), "r"(a[1]), "r"(a[2]), "r"(a[3]), "r"(b[0]), "r"(b[1]));
}

// Dequant byte sel of packed word w -> fp16x2 (k pair), scaled by sf2.
// fp16 pattern (s<<15)|(eem<<9) == fp4_value * 2^-14 exactly; sf2 = half2(scale*2^14).
__device__ __forceinline__ uint32_t dqb(uint32_t w, uint32_t sel, uint32_t sf2) {
    uint32_t t, r;
    asm("prmt.b32 %0, %1, %1, %2;" : "=r"(t) : "r"(w), "r"(sel));
    uint32_t h = ((t << 9) & 0x00000E00u) | ((t << 4) & 0x00008000u)
               | ((t << 5) & 0x0E000000u) | (t & 0x80000000u);
    asm("mul.f16x2 %0, %1, %2;" : "=r"(r) : "r"(h), "r"(sf2));
    return r;
}

// ---------------- prep: x f32 -> fp16 ------------------------------------
__global__ void __launch_bounds__(512) prep_x_kernel(const float* __restrict__ x) {
    int idx = blockIdx.x * 512 + threadIdx.x;
    g_xh[idx] = __float2half_rn(x[idx]);   // exact: x was fp16 originally
}

// ---------------- cp.async HMMA dequant-GEMM (R11 structure) --------------
// partial[n][b] += sum_k dequant(W[k][n]) * act[b][k]
template <int KDIM, bool PHASE1>
__global__ void __launch_bounds__(THREADS) gemm_mma_kernel(
    const int*   __restrict__ packed,   // [KDIM/8][NCOLS]
    const float* __restrict__ scales)   // [KDIM/GSZ][NCOLS]
{
    constexpr int NCH = (KDIM / KSPLIT) / KCHUNK;   // 4 (gemm1) / 2 (gemm2)

    __shared__ __align__(16) uint32_t Ap [STAGES][8 * MTILE];       // packed W, 8 KB
    __shared__ __align__(16) __half   Bsh[STAGES][BATCH * KCHUNK];  // 16 KB
    __shared__ __align__(16) float    Scs[STAGES][MTILE];           // 1 KB

    const int tid  = threadIdx.x;
    const int wid  = tid >> 5;
    const int lane = tid & 31;

    const int n_base  = blockIdx.x * MTILE;
    const int k_begin = blockIdx.y * (KDIM / KSPLIT);

    // ---- cp.async source/dst mapping ----
    // A: thread -> (k8 row r = tid>>4, 4 cols n4 = (tid&15)*4), one 16B copy
    const int r  = tid >> 4;
    const int n4 = (tid & 15) * 4;
    const uint32_t* asrc0 = (const uint32_t*)packed
                          + (size_t)((k_begin >> 3) + r) * NCOLS + n_base + n4;
    // B: thread -> (row brow = tid>>2, 2 16B chunks bcx2, bcx2+1), swizzled dst
    const int brow = tid >> 2;
    const int bcx2 = (tid & 3) * 2;
    const __half* __restrict__ Bsrc = PHASE1 ? g_xh : g_acth;
    const __half* bsrc0 = Bsrc + (size_t)brow * KDIM + k_begin + bcx2 * 8;
    uint32_t adst[STAGES], bdst[STAGES][2], sdst[STAGES];
    #pragma unroll
    for (int s = 0; s < STAGES; ++s) {
        adst[s] = smem_u32(&Ap[s][r * MTILE + n4]);
        bdst[s][0] = smem_u32(&Bsh[s][brow * KCHUNK + ((bcx2 ^ (brow & 7)) * 8)]);
        bdst[s][1] = smem_u32(&Bsh[s][brow * KCHUNK + (((bcx2 + 1) ^ (brow & 7)) * 8)]);
        sdst[s] = smem_u32(&Scs[s][(tid & 15) * 4]);
    }
    const float* ssrc_base = scales + (size_t)(k_begin >> 7) * NCOLS + n_base + (tid & 15) * 4;

    auto issue = [&](int c, int st) {
        CP16(adst[st], asrc0 + (size_t)c * 8 * NCOLS);
        CP16(bdst[st][0], bsrc0 + (size_t)c * KCHUNK);
        CP16(bdst[st][1], bsrc0 + (size_t)c * KCHUNK + 8);
        if (tid < 16)
            CP16(sdst[st], ssrc_base + (size_t)(c >> 1) * NCOLS);
    };

    // ---- prologue: up to 3 chunks in flight (uniform group count) ----
    issue(0, 0);              CP_COMMIT();
    if (NCH > 1) issue(1, 1); CP_COMMIT();
    if (NCH > 2) issue(2, 2); CP_COMMIT();

    // ---- MMA lane addressing ----
    float acc[4][4] = {};
    const int sub = lane >> 3, l7 = lane & 7;
    const int mrow = wid * 16;                 // warp's m16 slice of MTILE=64
    const int n0l  = mrow + (lane >> 2);       // A fragment rows (tile-local n)
    const int n1l  = n0l + 8;
    const uint32_t sel = (uint32_t)(lane & 3) * 0x1111u;
    const int bn0 = l7 + (sub >> 1) * 8;       // B ldmatrix row base
    const int bcx_off = sub & 1;

    #pragma unroll
    for (int c = 0; c < NCH; ++c) {
        CP_WAIT2();           // chunk c's group (and all before) complete
        __syncthreads();      // visible to all; prior compute on reused stage done
        if (c + 3 < NCH) issue(c + 3, (c + 3) & (STAGES - 1));
        CP_COMMIT();          // commit every iter (uniform group count)

        const int st = c & (STAGES - 1);
        const uint32_t* ap = &Ap[st][0];
        const uint32_t Bb = smem_u32(&Bsh[st][0]);

        // per-row scales for this k-group (2^14 folded, exact pow2)
        const uint32_t sf0 = (uint32_t)__half_as_ushort(
            __float2half_rn(Scs[st][n0l] * 16384.0f)) * 0x00010001u;
        const uint32_t sf1 = (uint32_t)__half_as_ushort(
            __float2half_rn(Scs[st][n1l] * 16384.0f)) * 0x00010001u;

        #pragma unroll
        for (int ks = 0; ks < 4; ++ks) {
            // A fragment: dequant directly from packed smem words
            uint32_t a[4];
            {
                const uint32_t w00 = ap[(2 * ks)     * MTILE + n0l];
                const uint32_t w10 = ap[(2 * ks)     * MTILE + n1l];
                const uint32_t w01 = ap[(2 * ks + 1) * MTILE + n0l];
                const uint32_t w11 = ap[(2 * ks + 1) * MTILE + n1l];
                a[0] = dqb(w00, sel, sf0);
                a[1] = dqb(w10, sel, sf1);
                a[2] = dqb(w01, sel, sf0);
                a[3] = dqb(w11, sel, sf1);
            }
            // B fragments
            uint32_t b0[4], b1[4];
            const int bcxs = ks * 2 + bcx_off;
            {
                const int n = bn0;
                ldsm_x4(b0[0], b0[1], b0[2], b0[3],
                        Bb + (uint32_t)(n * (KCHUNK * 2))
                           + (uint32_t)((bcxs ^ (n & 7)) << 4));
            }
            {
                const int n = bn0 + 16;
                ldsm_x4(b1[0], b1[1], b1[2], b1[3],
                        Bb + (uint32_t)(n * (KCHUNK * 2))
                           + (uint32_t)((bcxs ^ (n & 7)) << 4));
            }
            mma_16816(acc[0], a, &b0[0]);
            mma_16816(acc[1], a, &b0[2]);
            mma_16816(acc[2], a, &b1[0]);
            mma_16816(acc[3], a, &b1[2]);
        }
    }

    // ---- epilogue: D fragments -> partials [n][b] ----
    float* partp = (PHASE1 ? &g_hpart[0][0] : &g_opart[0][0])
                  + (size_t)blockIdx.y * (NCOLS * BATCH);
    const int gq = lane >> 2, tq = lane & 3;
    const int nrow0 = n_base + mrow + gq;
    #pragma unroll
    for (int t = 0; t < 4; ++t) {
        const int bcol = t * 8 + tq * 2;
        *(float2*)&partp[(size_t)nrow0 * BATCH + bcol]       = make_float2(acc[t][0], acc[t][1]);
        *(float2*)&partp[(size_t)(nrow0 + 8) * BATCH + bcol] = make_float2(acc[t][2], acc[t][3]);
    }
}

// ---------------- SwiGLU: reduce gemm1 partials -> act fp16 [b][i] -------
__global__ void __launch_bounds__(256) swiglu_kernel() {
    __shared__ float s_act[8][33];
    const int i0 = blockIdx.x * 8;
    const int b  = threadIdx.x & 31;
    const int il = threadIdx.x >> 5;          // 0..7
    {
        const size_t ng = (size_t)(i0 + il) * BATCH + b;
        float hg = 0.f, hu = 0.f;
        #pragma unroll
        for (int s = 0; s < KSPLIT; ++s) {
            hg += g_hpart[s][ng];
            hu += g_hpart[s][ng + (size_t)IDIM * BATCH];
        }
        const float sig = 1.0f / (1.0f + __expf(-hg));
        s_act[il][b] = hg * sig * hu;
    }
    __syncthreads();
    const int bb = threadIdx.x >> 3;          // 0..31
    const int pp = threadIdx.x & 3;           // 0..3 half2 pairs
    if ((threadIdx.x & 4) == 0) {
        __half2 h = __float22half2_rn(make_float2(s_act[pp * 2][bb], s_act[pp * 2 + 1][bb]));
        *(__half2*)&g_acth[(size_t)bb * IDIM + i0 + pp * 2] = h;
    }
}

// ---------------- reduce gemm2 partials [n][b] -> out [b][n] f32 ---------
__global__ void __launch_bounds__(256) reduce_out_kernel(float* __restrict__ out) {
    __shared__ float s_o[16][33];
    const int h0 = blockIdx.x * 16;
    const int b  = threadIdx.x & 31;
    const int hl = threadIdx.x >> 5;          // 0..7
    {
        const size_t ng0 = (size_t)(h0 + hl) * BATCH + b;
        const size_t ng1 = (size_t)(h0 + hl + 8) * BATCH + b;
        float s0 = 0.f, s1 = 0.f;
        #pragma unroll
        for (int sp = 0; sp < KSPLIT; ++sp) {
            s0 += g_opart[sp][ng0];
            s1 += g_opart[sp][ng1];
        }
        s_o[hl][b]     = s0;
        s_o[hl + 8][b] = s1;
    }
    __syncthreads();
    const int bb = threadIdx.x >> 3;          // 0..31
    const int h2 = threadIdx.x & 7;           // 0..7
    out[(size_t)bb * NCOLS + h0 + h2] =
        __half2float(__float2half_rn(s_o[h2][bb]));
    out[(size_t)bb * NCOLS + h0 + h2 + 8] =
        __half2float(__float2half_rn(s_o[h2 + 8][bb]));
}

// ---------------- launch --------------------------------------------------
extern "C" void kernel_launch(void* const* d_in, const int* in_sizes, int n_in,
                              void* d_out, int out_size) {
    const float* x   = (const float*)d_in[0];
    const int*   gup = (const int*)  d_in[1];
    const float* gus = (const float*)d_in[2];
    const int*   dwn = (const int*)  d_in[3];
    const float* dws = (const float*)d_in[4];
    float* out = (float*)d_out;

    prep_x_kernel<<<(BATCH * HDIM) / 512, 512>>>(x);

    gemm_mma_kernel<HDIM, true><<<dim3(NCOLS / MTILE, KSPLIT), THREADS>>>(gup, gus);

    swiglu_kernel<<<IDIM / 8, 256>>>();

    gemm_mma_kernel<IDIM, false><<<dim3(NCOLS / MTILE, KSPLIT), THREADS>>>(dwn, dws);

    reduce_out_kernel<<<NCOLS / 16, 256>>>(out);
}